// round 2
// baseline (speedup 1.0000x reference)
#include <cuda_runtime.h>
#include <math.h>

#define D_MODEL 1024
#define NHEAD   16
#define DEPTH   64
#define BATCH   4
#define SEQ     2048
#define MROWS   (BATCH * SEQ)      // 8192
#define NBH     (BATCH * NHEAD)    // 64
#define QSTRIDE 68                 // padded row stride (floats) for transposed smem tiles

// Scratch (alloc-free rule: __device__ globals). 4 x 32 MB.
__device__ float g_qh[NBH * SEQ * DEPTH];
__device__ float g_kh[NBH * SEQ * DEPTH];
__device__ float g_vh[NBH * SEQ * DEPTH];
__device__ float g_ao[MROWS * D_MODEL];

// ---------------------------------------------------------------------------
// SGEMM: C[M=8192, N=1024] = A[M,1024] @ W[1024,1024] + bias
// 64x64 block tile, BK=16, 256 threads, 4x4 micro-tile per thread.
// HEADSPLIT=true writes C in [B, H, S, 64] layout for the attention kernel.
// ---------------------------------------------------------------------------
template <bool HEADSPLIT>
__global__ void __launch_bounds__(256) gemm_bias_kernel(
    const float* __restrict__ A, const float* __restrict__ W,
    const float* __restrict__ bias, float* __restrict__ C)
{
    __shared__ float As[16][64];   // As[k][m]
    __shared__ float Ws[16][64];   // Ws[k][n]

    const int m0 = blockIdx.y * 64;
    const int n0 = blockIdx.x * 64;
    const int tid = threadIdx.x;
    const int tx = tid & 15;       // n-direction
    const int ty = tid >> 4;       // m-direction

    // load mapping: A tile 64 rows x 16 k (one float4 per thread)
    const int arow = tid >> 2;
    const int acol = (tid & 3) << 2;
    // W tile 16 k x 64 n (one float4 per thread)
    const int wrow = tid >> 4;
    const int wcol = (tid & 15) << 2;

    float acc[4][4];
#pragma unroll
    for (int i = 0; i < 4; i++)
#pragma unroll
        for (int j = 0; j < 4; j++) acc[i][j] = 0.f;

    const float* Aptr = A + (size_t)(m0 + arow) * D_MODEL + acol;
    const float* Wptr = W + (size_t)wrow * D_MODEL + n0 + wcol;

    for (int k0 = 0; k0 < D_MODEL; k0 += 16) {
        float4 av = *(const float4*)(Aptr + k0);
        As[acol + 0][arow] = av.x;
        As[acol + 1][arow] = av.y;
        As[acol + 2][arow] = av.z;
        As[acol + 3][arow] = av.w;
        *(float4*)&Ws[wrow][wcol] = *(const float4*)(Wptr + (size_t)k0 * D_MODEL);
        __syncthreads();

#pragma unroll
        for (int kk = 0; kk < 16; kk++) {
            float4 a = *(const float4*)&As[kk][ty << 2];
            float4 b = *(const float4*)&Ws[kk][tx << 2];
            acc[0][0] += a.x * b.x; acc[0][1] += a.x * b.y; acc[0][2] += a.x * b.z; acc[0][3] += a.x * b.w;
            acc[1][0] += a.y * b.x; acc[1][1] += a.y * b.y; acc[1][2] += a.y * b.z; acc[1][3] += a.y * b.w;
            acc[2][0] += a.z * b.x; acc[2][1] += a.z * b.y; acc[2][2] += a.z * b.z; acc[2][3] += a.z * b.w;
            acc[3][0] += a.w * b.x; acc[3][1] += a.w * b.y; acc[3][2] += a.w * b.z; acc[3][3] += a.w * b.w;
        }
        __syncthreads();
    }

    const int n = n0 + (tx << 2);
    float4 bv = *(const float4*)&bias[n];
#pragma unroll
    for (int ii = 0; ii < 4; ii++) {
        const int row = m0 + (ty << 2) + ii;
        float4 r = make_float4(acc[ii][0] + bv.x, acc[ii][1] + bv.y,
                               acc[ii][2] + bv.z, acc[ii][3] + bv.w);
        if (HEADSPLIT) {
            const int h = n >> 6, d = n & 63;
            const int b = row >> 11, s = row & 2047;
            *(float4*)&C[(((size_t)(b * NHEAD + h) * SEQ) + s) * DEPTH + d] = r;
        } else {
            *(float4*)&C[(size_t)row * D_MODEL + n] = r;
        }
    }
}

// ---------------------------------------------------------------------------
// Flash attention: per block = one (b,h) x 64-query tile. Loops 64-key chunks.
// Online softmax; P staged through smem for the PV product.
// ---------------------------------------------------------------------------
__global__ void __launch_bounds__(256) attn_kernel(
    const float* __restrict__ qh, const float* __restrict__ kh,
    const float* __restrict__ vh, float* __restrict__ ao)
{
    extern __shared__ float sm[];
    float* Qt = sm;                       // [64 d][68]   (d-major, scaled)
    float* Kt = Qt + 64 * QSTRIDE;        // [64 d][68]
    float* Pt = Kt + 64 * QSTRIDE;        // [64 j][68]   Pt[j][i]
    float* Vs = Pt + 64 * QSTRIDE;        // [64 j][64 d]

    const int bh = blockIdx.y;            // 0..63
    const int q0 = blockIdx.x * 64;
    const float* Qg = qh + ((size_t)bh * SEQ + q0) * DEPTH;
    const float* Kg = kh + (size_t)bh * SEQ * DEPTH;
    const float* Vg = vh + (size_t)bh * SEQ * DEPTH;

    const int tid = threadIdx.x;
    const int tx = tid & 15;              // j / d-out direction
    const int ty = tid >> 4;              // i (query) direction
    const int lr = tid >> 2;              // loader: row 0..63
    const int lc = (tid & 3) << 4;        // loader: 16-wide col group

    // Load Q transposed + fold in softmax scale 1/sqrt(64)
#pragma unroll
    for (int u = 0; u < 4; u++) {
        const int d = lc + (u << 2);
        float4 v = *(const float4*)&Qg[lr * DEPTH + d];
        Qt[(d + 0) * QSTRIDE + lr] = v.x * 0.125f;
        Qt[(d + 1) * QSTRIDE + lr] = v.y * 0.125f;
        Qt[(d + 2) * QSTRIDE + lr] = v.z * 0.125f;
        Qt[(d + 3) * QSTRIDE + lr] = v.w * 0.125f;
    }

    float m_i[4], l_i[4], o[4][4];
#pragma unroll
    for (int ii = 0; ii < 4; ii++) {
        m_i[ii] = -INFINITY; l_i[ii] = 0.f;
#pragma unroll
        for (int jj = 0; jj < 4; jj++) o[ii][jj] = 0.f;
    }
    __syncthreads();

    for (int kc = 0; kc < SEQ; kc += 64) {
        // Stage K (transposed) and V (natural)
#pragma unroll
        for (int u = 0; u < 4; u++) {
            const int d = lc + (u << 2);
            float4 kv = *(const float4*)&Kg[(size_t)(kc + lr) * DEPTH + d];
            Kt[(d + 0) * QSTRIDE + lr] = kv.x;
            Kt[(d + 1) * QSTRIDE + lr] = kv.y;
            Kt[(d + 2) * QSTRIDE + lr] = kv.z;
            Kt[(d + 3) * QSTRIDE + lr] = kv.w;
            *(float4*)&Vs[lr * 64 + d] = *(const float4*)&Vg[(size_t)(kc + lr) * DEPTH + d];
        }
        __syncthreads();

        // S = Q K^T (scaled)
        float s[4][4];
#pragma unroll
        for (int i = 0; i < 4; i++)
#pragma unroll
            for (int j = 0; j < 4; j++) s[i][j] = 0.f;

#pragma unroll 8
        for (int d = 0; d < 64; d++) {
            float4 qa = *(const float4*)&Qt[d * QSTRIDE + (ty << 2)];
            float4 kb = *(const float4*)&Kt[d * QSTRIDE + (tx << 2)];
            s[0][0] += qa.x * kb.x; s[0][1] += qa.x * kb.y; s[0][2] += qa.x * kb.z; s[0][3] += qa.x * kb.w;
            s[1][0] += qa.y * kb.x; s[1][1] += qa.y * kb.y; s[1][2] += qa.y * kb.z; s[1][3] += qa.y * kb.w;
            s[2][0] += qa.z * kb.x; s[2][1] += qa.z * kb.y; s[2][2] += qa.z * kb.z; s[2][3] += qa.z * kb.w;
            s[3][0] += qa.w * kb.x; s[3][1] += qa.w * kb.y; s[3][2] += qa.w * kb.z; s[3][3] += qa.w * kb.w;
        }

        // Online softmax update (row reduction across 16 tx-lanes)
        float mnew[4], alpha[4];
#pragma unroll
        for (int ii = 0; ii < 4; ii++) {
            float mx = fmaxf(fmaxf(s[ii][0], s[ii][1]), fmaxf(s[ii][2], s[ii][3]));
#pragma unroll
            for (int w = 8; w >= 1; w >>= 1)
                mx = fmaxf(mx, __shfl_xor_sync(0xffffffffu, mx, w));
            mnew[ii] = fmaxf(m_i[ii], mx);
            alpha[ii] = __expf(m_i[ii] - mnew[ii]);
        }
#pragma unroll
        for (int ii = 0; ii < 4; ii++) {
            float r = 0.f;
#pragma unroll
            for (int jj = 0; jj < 4; jj++) {
                s[ii][jj] = __expf(s[ii][jj] - mnew[ii]);
                r += s[ii][jj];
            }
#pragma unroll
            for (int w = 8; w >= 1; w >>= 1)
                r += __shfl_xor_sync(0xffffffffu, r, w);
            l_i[ii] = l_i[ii] * alpha[ii] + r;
            m_i[ii] = mnew[ii];
#pragma unroll
            for (int jj = 0; jj < 4; jj++) o[ii][jj] *= alpha[ii];
        }

        // Stage P transposed: Pt[j][i]
#pragma unroll
        for (int jj = 0; jj < 4; jj++) {
            *(float4*)&Pt[((tx << 2) + jj) * QSTRIDE + (ty << 2)] =
                make_float4(s[0][jj], s[1][jj], s[2][jj], s[3][jj]);
        }
        __syncthreads();

        // O += P V
#pragma unroll 8
        for (int j = 0; j < 64; j++) {
            float4 pv = *(const float4*)&Pt[j * QSTRIDE + (ty << 2)];
            float4 vv = *(const float4*)&Vs[j * 64 + (tx << 2)];
            o[0][0] += pv.x * vv.x; o[0][1] += pv.x * vv.y; o[0][2] += pv.x * vv.z; o[0][3] += pv.x * vv.w;
            o[1][0] += pv.y * vv.x; o[1][1] += pv.y * vv.y; o[1][2] += pv.y * vv.z; o[1][3] += pv.y * vv.w;
            o[2][0] += pv.z * vv.x; o[2][1] += pv.z * vv.y; o[2][2] += pv.z * vv.z; o[2][3] += pv.z * vv.w;
            o[3][0] += pv.w * vv.x; o[3][1] += pv.w * vv.y; o[3][2] += pv.w * vv.z; o[3][3] += pv.w * vv.w;
        }
        __syncthreads();
    }

    // Epilogue: normalize and write merged-head layout [B, S, D_MODEL]
    const int b = bh >> 4, h = bh & 15;
#pragma unroll
    for (int ii = 0; ii < 4; ii++) {
        const int srow = q0 + (ty << 2) + ii;
        const float inv = 1.f / l_i[ii];
        float4 r = make_float4(o[ii][0] * inv, o[ii][1] * inv,
                               o[ii][2] * inv, o[ii][3] * inv);
        *(float4*)&ao[((size_t)(b * SEQ + srow)) * D_MODEL + h * DEPTH + (tx << 2)] = r;
    }
}

// ---------------------------------------------------------------------------
extern "C" void kernel_launch(void* const* d_in, const int* in_sizes, int n_in,
                              void* d_out, int out_size)
{
    const float* v  = (const float*)d_in[0];
    const float* k  = (const float*)d_in[1];
    const float* q  = (const float*)d_in[2];
    const float* wq = (const float*)d_in[3];
    const float* bq = (const float*)d_in[4];
    const float* wk = (const float*)d_in[5];
    const float* bk = (const float*)d_in[6];
    const float* wv = (const float*)d_in[7];
    const float* bv = (const float*)d_in[8];
    const float* wo = (const float*)d_in[9];
    const float* bo = (const float*)d_in[10];
    float* out = (float*)d_out;

    float *qh, *kh, *vh, *ao;
    cudaGetSymbolAddress((void**)&qh, g_qh);
    cudaGetSymbolAddress((void**)&kh, g_kh);
    cudaGetSymbolAddress((void**)&vh, g_vh);
    cudaGetSymbolAddress((void**)&ao, g_ao);

    const dim3 gg(D_MODEL / 64, MROWS / 64);   // (16, 128)

    gemm_bias_kernel<true><<<gg, 256>>>(q, wq, bq, qh);
    gemm_bias_kernel<true><<<gg, 256>>>(k, wk, bk, kh);
    gemm_bias_kernel<true><<<gg, 256>>>(v, wv, bv, vh);

    const int smem = (3 * 64 * QSTRIDE + 64 * 64) * (int)sizeof(float);  // 68608 B
    cudaFuncSetAttribute(attn_kernel, cudaFuncAttributeMaxDynamicSharedMemorySize, smem);
    attn_kernel<<<dim3(SEQ / 64, NBH), 256, smem>>>(qh, kh, vh, ao);

    gemm_bias_kernel<false><<<gg, 256>>>(ao, wo, bo, out);
}

// round 3
// speedup vs baseline: 1.5134x; 1.5134x over previous
#include <cuda_runtime.h>
#include <cuda_bf16.h>
#include <math.h>

#define D_MODEL 1024
#define NHEAD   16
#define DEPTH   64
#define BATCH   4
#define SEQ     2048
#define MROWS   (BATCH * SEQ)      // 8192
#define NBH     (BATCH * NHEAD)    // 64

typedef __nv_bfloat16 bf16;

// Scratch (alloc-free rule: __device__ globals).
__device__ float g_qh[NBH * SEQ * DEPTH];
__device__ float g_kh[NBH * SEQ * DEPTH];
__device__ float g_vh[NBH * SEQ * DEPTH];
__device__ float g_ao[MROWS * D_MODEL];

// ---------------------------------------------------------------------------
// mma.m16n8k16 bf16 (fp32 accum)
// ---------------------------------------------------------------------------
__device__ __forceinline__ void mma_bf16(float c[4], const unsigned a[4], const unsigned b[2])
{
    asm("mma.sync.aligned.m16n8k16.row.col.f32.bf16.bf16.f32 "
        "{%0,%1,%2,%3}, {%4,%5,%6,%7}, {%8,%9}, {%0,%1,%2,%3};"
        : "+f"(c[0]), "+f"(c[1]), "+f"(c[2]), "+f"(c[3])
        : "r"(a[0]), "r"(a[1]), "r"(a[2]), "r"(a[3]), "r"(b[0]), "r"(b[1]));
}

// split fp32 -> (hi bf16, lo bf16); exact two-term split (Sterbenz)
__device__ __forceinline__ void split1(float x, bf16& h, bf16& l)
{
    h = __float2bfloat16(x);
    l = __float2bfloat16(x - __bfloat162float(h));
}

// split a pair, pack as u32 (elem0 in low 16 bits = mma packing order)
__device__ __forceinline__ void split2(float x, float y, unsigned& h, unsigned& l)
{
    bf16 hx, lx, hy, ly;
    split1(x, hx, lx);
    split1(y, hy, ly);
    h = ((unsigned)__bfloat16_as_ushort(hy) << 16) | (unsigned)__bfloat16_as_ushort(hx);
    l = ((unsigned)__bfloat16_as_ushort(ly) << 16) | (unsigned)__bfloat16_as_ushort(lx);
}

// ---------------------------------------------------------------------------
// Tensor-core GEMM: C[8192,1024] = A[8192,1024] @ W[1024,1024] + bias
// 128x128 block tile, BK=32, 8 warps (2m x 4n), warp tile 64x32.
// Operands staged in smem as bf16 hi/lo planes; 3-pass bf16x2 MMA.
// ---------------------------------------------------------------------------
#define BKP 34                      // k-pitch (bf16 elems) for A/B smem rows
#define GTS (128 * BKP)             // one plane

__device__ __forceinline__ void gemm_store_tile(
    bf16* sm, int buf, const float4* pa, const float4* pw,
    int ar, int ac, int wk, int wn4)
{
    bf16* Ah = sm + (size_t)buf * 4 * GTS;
    bf16* Al = Ah + GTS;
    bf16* Bh = Al + GTS;
    bf16* Bl = Bh + GTS;
#pragma unroll
    for (int i = 0; i < 4; i++) {
        const int r = ar + 32 * i;
        unsigned h, l;
        split2(pa[i].x, pa[i].y, h, l);
        *(unsigned*)&Ah[r * BKP + ac] = h;
        *(unsigned*)&Al[r * BKP + ac] = l;
        split2(pa[i].z, pa[i].w, h, l);
        *(unsigned*)&Ah[r * BKP + ac + 2] = h;
        *(unsigned*)&Al[r * BKP + ac + 2] = l;

        const int k = wk + 8 * i;
        bf16 hh, ll;
        split1(pw[i].x, hh, ll); Bh[(wn4 + 0) * BKP + k] = hh; Bl[(wn4 + 0) * BKP + k] = ll;
        split1(pw[i].y, hh, ll); Bh[(wn4 + 1) * BKP + k] = hh; Bl[(wn4 + 1) * BKP + k] = ll;
        split1(pw[i].z, hh, ll); Bh[(wn4 + 2) * BKP + k] = hh; Bl[(wn4 + 2) * BKP + k] = ll;
        split1(pw[i].w, hh, ll); Bh[(wn4 + 3) * BKP + k] = hh; Bl[(wn4 + 3) * BKP + k] = ll;
    }
}

template <bool HEADSPLIT>
__global__ void __launch_bounds__(256) gemm_tc(
    const float* __restrict__ A, const float* __restrict__ W,
    const float* __restrict__ bias, float* __restrict__ C)
{
    extern __shared__ bf16 smg[];

    const int m0 = blockIdx.y * 128;
    const int n0 = blockIdx.x * 128;
    const int tid  = threadIdx.x;
    const int lane = tid & 31, warp = tid >> 5;
    const int g = lane >> 2, tig = lane & 3;
    const int wm = warp >> 2, wn = warp & 3;   // 2 x 4 warp grid

    // staging thread mapping
    const int ar  = tid >> 3;           // 0..31  (A row)
    const int ac  = (tid & 7) * 4;      // 0..28  (A k-col, float4)
    const int wk  = tid >> 5;           // 0..7   (W k-row)
    const int wn4 = (tid & 31) * 4;     // 0..124 (W n-col, float4)

    float acc[4][4][4];
#pragma unroll
    for (int i = 0; i < 4; i++)
#pragma unroll
        for (int j = 0; j < 4; j++)
#pragma unroll
            for (int c = 0; c < 4; c++) acc[i][j][c] = 0.f;

    float4 pa[4], pw[4];
#pragma unroll
    for (int i = 0; i < 4; i++) {
        pa[i] = *(const float4*)&A[(size_t)(m0 + ar + 32 * i) * D_MODEL + ac];
        pw[i] = *(const float4*)&W[(size_t)(wk + 8 * i) * D_MODEL + n0 + wn4];
    }
    gemm_store_tile(smg, 0, pa, pw, ar, ac, wk, wn4);
    __syncthreads();

    for (int kt = 0; kt < 32; kt++) {
        const int cur = kt & 1;
        const bool has_next = (kt < 31);
        if (has_next) {
            const int k0 = (kt + 1) * 32;
#pragma unroll
            for (int i = 0; i < 4; i++) {
                pa[i] = *(const float4*)&A[(size_t)(m0 + ar + 32 * i) * D_MODEL + k0 + ac];
                pw[i] = *(const float4*)&W[(size_t)(k0 + wk + 8 * i) * D_MODEL + n0 + wn4];
            }
        }

        const bf16* Ah = smg + (size_t)cur * 4 * GTS;
        const bf16* Al = Ah + GTS;
        const bf16* Bh = Al + GTS;
        const bf16* Bl = Bh + GTS;

#pragma unroll
        for (int kk = 0; kk < 2; kk++) {
            const int c0 = kk * 16 + 2 * tig;
            unsigned ah[4][4], af[4][4], bh_[4][2], bl_[4][2];
#pragma unroll
            for (int ma = 0; ma < 4; ma++) {
                const int r = wm * 64 + ma * 16 + g;
                ah[ma][0] = *(const unsigned*)&Ah[r * BKP + c0];
                ah[ma][1] = *(const unsigned*)&Ah[(r + 8) * BKP + c0];
                ah[ma][2] = *(const unsigned*)&Ah[r * BKP + c0 + 8];
                ah[ma][3] = *(const unsigned*)&Ah[(r + 8) * BKP + c0 + 8];
                af[ma][0] = *(const unsigned*)&Al[r * BKP + c0];
                af[ma][1] = *(const unsigned*)&Al[(r + 8) * BKP + c0];
                af[ma][2] = *(const unsigned*)&Al[r * BKP + c0 + 8];
                af[ma][3] = *(const unsigned*)&Al[(r + 8) * BKP + c0 + 8];
            }
#pragma unroll
            for (int na = 0; na < 4; na++) {
                const int n = wn * 32 + na * 8 + g;
                bh_[na][0] = *(const unsigned*)&Bh[n * BKP + c0];
                bh_[na][1] = *(const unsigned*)&Bh[n * BKP + c0 + 8];
                bl_[na][0] = *(const unsigned*)&Bl[n * BKP + c0];
                bl_[na][1] = *(const unsigned*)&Bl[n * BKP + c0 + 8];
            }
#pragma unroll
            for (int ma = 0; ma < 4; ma++)
#pragma unroll
                for (int na = 0; na < 4; na++) {
                    mma_bf16(acc[ma][na], ah[ma], bh_[na]);
                    mma_bf16(acc[ma][na], ah[ma], bl_[na]);
                    mma_bf16(acc[ma][na], af[ma], bh_[na]);
                }
        }

        if (has_next)
            gemm_store_tile(smg, cur ^ 1, pa, pw, ar, ac, wk, wn4);
        __syncthreads();
    }

    // epilogue
#pragma unroll
    for (int ma = 0; ma < 4; ma++) {
        const int m_r = m0 + wm * 64 + ma * 16 + g;
#pragma unroll
        for (int na = 0; na < 4; na++) {
            const int n = n0 + wn * 32 + na * 8 + 2 * tig;
            const float2 bv = *(const float2*)&bias[n];
            float2 r0 = make_float2(acc[ma][na][0] + bv.x, acc[ma][na][1] + bv.y);
            float2 r1 = make_float2(acc[ma][na][2] + bv.x, acc[ma][na][3] + bv.y);
            if (HEADSPLIT) {
                const int h = n >> 6, d = n & 63;
                const int b0 = m_r >> 11, s0 = m_r & 2047;
                *(float2*)&C[(((size_t)(b0 * NHEAD + h) * SEQ) + s0) * DEPTH + d] = r0;
                const int m1 = m_r + 8;
                const int b1 = m1 >> 11, s1 = m1 & 2047;
                *(float2*)&C[(((size_t)(b1 * NHEAD + h) * SEQ) + s1) * DEPTH + d] = r1;
            } else {
                *(float2*)&C[(size_t)m_r * D_MODEL + n] = r0;
                *(float2*)&C[(size_t)(m_r + 8) * D_MODEL + n] = r1;
            }
        }
    }
}

// ---------------------------------------------------------------------------
// Tensor-core flash attention. Block = (bh, 128-query tile). 8 warps, each
// owns 16 query rows (pure m-split => softmax row stats live inside a quad).
// 64-key chunks; K/V/P staged in smem as bf16 hi/lo planes.
// ---------------------------------------------------------------------------
#define KP 66

__global__ void __launch_bounds__(256) attn_tc(
    const float* __restrict__ qh, const float* __restrict__ kh,
    const float* __restrict__ vh, float* __restrict__ ao)
{
    extern __shared__ bf16 sma[];
    bf16* Kh  = sma;                 // [64 key][KP d]
    bf16* Kl  = Kh  + 64 * KP;
    bf16* Vth = Kl  + 64 * KP;       // [64 d][KP key]  (transposed)
    bf16* Vtl = Vth + 64 * KP;
    bf16* Ph  = Vtl + 64 * KP;       // [128 q][KP key]
    bf16* Pl  = Ph  + 128 * KP;

    const int bh = blockIdx.y;
    const int q0 = blockIdx.x * 128;
    const int tid  = threadIdx.x;
    const int lane = tid & 31, warp = tid >> 5;
    const int g = lane >> 2, tig = lane & 3;
    const int w16 = warp * 16;

    const float* Qg = qh + ((size_t)bh * SEQ + q0) * DEPTH;
    const float* Kg = kh + (size_t)bh * SEQ * DEPTH;
    const float* Vg = vh + (size_t)bh * SEQ * DEPTH;

    // Q fragments in registers, softmax scale 1/8 folded in
    unsigned qfh[4][4], qfl[4][4];
#pragma unroll
    for (int ks = 0; ks < 4; ks++) {
        const int c = ks * 16 + 2 * tig;
        float2 x0 = *(const float2*)&Qg[(w16 + g)     * DEPTH + c];
        float2 x1 = *(const float2*)&Qg[(w16 + g + 8) * DEPTH + c];
        float2 x2 = *(const float2*)&Qg[(w16 + g)     * DEPTH + c + 8];
        float2 x3 = *(const float2*)&Qg[(w16 + g + 8) * DEPTH + c + 8];
        split2(x0.x * 0.125f, x0.y * 0.125f, qfh[ks][0], qfl[ks][0]);
        split2(x1.x * 0.125f, x1.y * 0.125f, qfh[ks][1], qfl[ks][1]);
        split2(x2.x * 0.125f, x2.y * 0.125f, qfh[ks][2], qfl[ks][2]);
        split2(x3.x * 0.125f, x3.y * 0.125f, qfh[ks][3], qfl[ks][3]);
    }

    float o[8][4];
#pragma unroll
    for (int na = 0; na < 8; na++)
#pragma unroll
        for (int c = 0; c < 4; c++) o[na][c] = 0.f;
    float m0r = -INFINITY, m1r = -INFINITY, l0 = 0.f, l1 = 0.f;

    const int kr = tid >> 2;             // 0..63 (staging row)
    const int kc4 = (tid & 3) * 16;      // staging col group

    for (int kc = 0; kc < SEQ; kc += 64) {
        // ---- stage K (natural) and V (transposed), split hi/lo ----
#pragma unroll
        for (int i = 0; i < 4; i++) {
            const int c = kc4 + 4 * i;
            float4 kv = *(const float4*)&Kg[(size_t)(kc + kr) * DEPTH + c];
            unsigned h, l;
            split2(kv.x, kv.y, h, l);
            *(unsigned*)&Kh[kr * KP + c] = h;     *(unsigned*)&Kl[kr * KP + c] = l;
            split2(kv.z, kv.w, h, l);
            *(unsigned*)&Kh[kr * KP + c + 2] = h; *(unsigned*)&Kl[kr * KP + c + 2] = l;

            float4 vv = *(const float4*)&Vg[(size_t)(kc + kr) * DEPTH + c];
            bf16 hh, ll;
            split1(vv.x, hh, ll); Vth[(c + 0) * KP + kr] = hh; Vtl[(c + 0) * KP + kr] = ll;
            split1(vv.y, hh, ll); Vth[(c + 1) * KP + kr] = hh; Vtl[(c + 1) * KP + kr] = ll;
            split1(vv.z, hh, ll); Vth[(c + 2) * KP + kr] = hh; Vtl[(c + 2) * KP + kr] = ll;
            split1(vv.w, hh, ll); Vth[(c + 3) * KP + kr] = hh; Vtl[(c + 3) * KP + kr] = ll;
        }
        __syncthreads();

        // ---- S = Q K^T ----
        float s[8][4];
#pragma unroll
        for (int na = 0; na < 8; na++)
#pragma unroll
            for (int c = 0; c < 4; c++) s[na][c] = 0.f;

#pragma unroll
        for (int ks = 0; ks < 4; ks++) {
            const int c0 = ks * 16 + 2 * tig;
            unsigned kbh[8][2], kbl[8][2];
#pragma unroll
            for (int na = 0; na < 8; na++) {
                const int n = na * 8 + g;
                kbh[na][0] = *(const unsigned*)&Kh[n * KP + c0];
                kbh[na][1] = *(const unsigned*)&Kh[n * KP + c0 + 8];
                kbl[na][0] = *(const unsigned*)&Kl[n * KP + c0];
                kbl[na][1] = *(const unsigned*)&Kl[n * KP + c0 + 8];
            }
#pragma unroll
            for (int na = 0; na < 8; na++) {
                mma_bf16(s[na], qfh[ks], kbh[na]);
                mma_bf16(s[na], qfh[ks], kbl[na]);
                mma_bf16(s[na], qfl[ks], kbh[na]);
            }
        }

        // ---- online softmax (rows g and g+8; reduce across quad) ----
        float mx0 = -INFINITY, mx1 = -INFINITY;
#pragma unroll
        for (int na = 0; na < 8; na++) {
            mx0 = fmaxf(mx0, fmaxf(s[na][0], s[na][1]));
            mx1 = fmaxf(mx1, fmaxf(s[na][2], s[na][3]));
        }
        mx0 = fmaxf(mx0, __shfl_xor_sync(0xffffffffu, mx0, 1));
        mx0 = fmaxf(mx0, __shfl_xor_sync(0xffffffffu, mx0, 2));
        mx1 = fmaxf(mx1, __shfl_xor_sync(0xffffffffu, mx1, 1));
        mx1 = fmaxf(mx1, __shfl_xor_sync(0xffffffffu, mx1, 2));

        const float mn0 = fmaxf(m0r, mx0), mn1 = fmaxf(m1r, mx1);
        const float a0 = __expf(m0r - mn0), a1 = __expf(m1r - mn1);
        m0r = mn0; m1r = mn1;

        float r0 = 0.f, r1 = 0.f;
#pragma unroll
        for (int na = 0; na < 8; na++) {
            s[na][0] = __expf(s[na][0] - mn0);
            s[na][1] = __expf(s[na][1] - mn0);
            s[na][2] = __expf(s[na][2] - mn1);
            s[na][3] = __expf(s[na][3] - mn1);
            r0 += s[na][0] + s[na][1];
            r1 += s[na][2] + s[na][3];
        }
        r0 += __shfl_xor_sync(0xffffffffu, r0, 1);
        r0 += __shfl_xor_sync(0xffffffffu, r0, 2);
        r1 += __shfl_xor_sync(0xffffffffu, r1, 1);
        r1 += __shfl_xor_sync(0xffffffffu, r1, 2);
        l0 = l0 * a0 + r0;
        l1 = l1 * a1 + r1;
#pragma unroll
        for (int na = 0; na < 8; na++) {
            o[na][0] *= a0; o[na][1] *= a0;
            o[na][2] *= a1; o[na][3] *= a1;
        }

        // ---- stage P (split hi/lo) ----
#pragma unroll
        for (int na = 0; na < 8; na++) {
            const int c = na * 8 + 2 * tig;
            unsigned h, l;
            split2(s[na][0], s[na][1], h, l);
            *(unsigned*)&Ph[(w16 + g) * KP + c] = h;
            *(unsigned*)&Pl[(w16 + g) * KP + c] = l;
            split2(s[na][2], s[na][3], h, l);
            *(unsigned*)&Ph[(w16 + g + 8) * KP + c] = h;
            *(unsigned*)&Pl[(w16 + g + 8) * KP + c] = l;
        }
        __syncthreads();

        // ---- O += P V ----
#pragma unroll
        for (int ks = 0; ks < 4; ks++) {
            const int c0 = ks * 16 + 2 * tig;
            unsigned ap[4], af[4];
            ap[0] = *(const unsigned*)&Ph[(w16 + g)     * KP + c0];
            ap[1] = *(const unsigned*)&Ph[(w16 + g + 8) * KP + c0];
            ap[2] = *(const unsigned*)&Ph[(w16 + g)     * KP + c0 + 8];
            ap[3] = *(const unsigned*)&Ph[(w16 + g + 8) * KP + c0 + 8];
            af[0] = *(const unsigned*)&Pl[(w16 + g)     * KP + c0];
            af[1] = *(const unsigned*)&Pl[(w16 + g + 8) * KP + c0];
            af[2] = *(const unsigned*)&Pl[(w16 + g)     * KP + c0 + 8];
            af[3] = *(const unsigned*)&Pl[(w16 + g + 8) * KP + c0 + 8];
#pragma unroll
            for (int na = 0; na < 8; na++) {
                const int n = na * 8 + g;
                unsigned vb[2], vl[2];
                vb[0] = *(const unsigned*)&Vth[n * KP + c0];
                vb[1] = *(const unsigned*)&Vth[n * KP + c0 + 8];
                vl[0] = *(const unsigned*)&Vtl[n * KP + c0];
                vl[1] = *(const unsigned*)&Vtl[n * KP + c0 + 8];
                mma_bf16(o[na], ap, vb);
                mma_bf16(o[na], ap, vl);
                mma_bf16(o[na], af, vb);
            }
        }
        __syncthreads();
    }

    // ---- epilogue: normalize, write merged-head layout [B, S, D_MODEL] ----
    const int b = bh >> 4, h = bh & 15;
    const float i0 = 1.f / l0, i1 = 1.f / l1;
    const int row0 = q0 + w16 + g;
#pragma unroll
    for (int na = 0; na < 8; na++) {
        const int d = h * 64 + na * 8 + 2 * tig;
        float2 v0 = make_float2(o[na][0] * i0, o[na][1] * i0);
        float2 v1 = make_float2(o[na][2] * i1, o[na][3] * i1);
        *(float2*)&ao[(size_t)(b * SEQ + row0)     * D_MODEL + d] = v0;
        *(float2*)&ao[(size_t)(b * SEQ + row0 + 8) * D_MODEL + d] = v1;
    }
}

// ---------------------------------------------------------------------------
extern "C" void kernel_launch(void* const* d_in, const int* in_sizes, int n_in,
                              void* d_out, int out_size)
{
    const float* v  = (const float*)d_in[0];
    const float* k  = (const float*)d_in[1];
    const float* q  = (const float*)d_in[2];
    const float* wq = (const float*)d_in[3];
    const float* bq = (const float*)d_in[4];
    const float* wk = (const float*)d_in[5];
    const float* bk = (const float*)d_in[6];
    const float* wv = (const float*)d_in[7];
    const float* bv = (const float*)d_in[8];
    const float* wo = (const float*)d_in[9];
    const float* bo = (const float*)d_in[10];
    float* out = (float*)d_out;

    float *qh, *kh, *vh, *ao;
    cudaGetSymbolAddress((void**)&qh, g_qh);
    cudaGetSymbolAddress((void**)&kh, g_kh);
    cudaGetSymbolAddress((void**)&vh, g_vh);
    cudaGetSymbolAddress((void**)&ao, g_ao);

    const int gemm_smem = 2 * 4 * GTS * (int)sizeof(bf16);            // 69632
    const int attn_smem = (4 * 64 * KP + 2 * 128 * KP) * (int)sizeof(bf16); // 67584
    cudaFuncSetAttribute(gemm_tc<true>,  cudaFuncAttributeMaxDynamicSharedMemorySize, gemm_smem);
    cudaFuncSetAttribute(gemm_tc<false>, cudaFuncAttributeMaxDynamicSharedMemorySize, gemm_smem);
    cudaFuncSetAttribute(attn_tc, cudaFuncAttributeMaxDynamicSharedMemorySize, attn_smem);

    const dim3 gg(D_MODEL / 128, MROWS / 128);   // (8, 64)

    gemm_tc<true><<<gg, 256, gemm_smem>>>(q, wq, bq, qh);
    gemm_tc<true><<<gg, 256, gemm_smem>>>(k, wk, bk, kh);
    gemm_tc<true><<<gg, 256, gemm_smem>>>(v, wv, bv, vh);

    attn_tc<<<dim3(SEQ / 128, NBH), 256, attn_smem>>>(qh, kh, vh, ao);

    gemm_tc<false><<<gg, 256, gemm_smem>>>(ao, wo, bo, out);
}

// round 5
// speedup vs baseline: 3.3764x; 2.2310x over previous
#include <cuda_runtime.h>
#include <cuda_bf16.h>
#include <math.h>

typedef unsigned int u32;
typedef unsigned short u16;

#define D_MODEL 1024
#define NHEAD   16
#define DEPTH   64
#define BATCH   4
#define SEQ     2048
#define MROWS   (BATCH * SEQ)       // 8192
#define NBH     (BATCH * NHEAD)     // 64
#define INN     (MROWS * D_MODEL)   // 8388608
#define WN      (D_MODEL * D_MODEL)
#define PROJN   (NBH * SEQ * DEPTH) // 8388608

// ---------------- global scratch (alloc-free rule) -------------------------
__device__ u16 g_xh[3][INN],  g_xl[3][INN];    // split q/k/v inputs
__device__ u16 g_wh[4][WN],   g_wl[4][WN];     // split wq/wk/wv/wo
__device__ u16 g_ph[3][PROJN], g_pl[3][PROJN]; // projected qh/kh/vh planes
__device__ u16 g_oh[INN],     g_ol[INN];       // attention output planes

// ---------------- primitives ----------------------------------------------
__device__ __forceinline__ void mma_bf16(float c[4], const u32 a[4], const u32 b[2])
{
    asm("mma.sync.aligned.m16n8k16.row.col.f32.bf16.bf16.f32 "
        "{%0,%1,%2,%3}, {%4,%5,%6,%7}, {%8,%9}, {%0,%1,%2,%3};"
        : "+f"(c[0]), "+f"(c[1]), "+f"(c[2]), "+f"(c[3])
        : "r"(a[0]), "r"(a[1]), "r"(a[2]), "r"(a[3]), "r"(b[0]), "r"(b[1]));
}

struct HL { u32 h, l; };
// split (x,y) fp32 pair into packed bf16x2 hi and lo planes (low half = x)
__device__ __forceinline__ HL split2f(float x, float y)
{
    HL r;
    asm("cvt.rn.bf16x2.f32 %0, %1, %2;" : "=r"(r.h) : "f"(y), "f"(x));
    float xh = __uint_as_float(r.h << 16);
    float yh = __uint_as_float(r.h & 0xffff0000u);
    asm("cvt.rn.bf16x2.f32 %0, %1, %2;" : "=r"(r.l) : "f"(y - yh), "f"(x - xh));
    return r;
}

__device__ __forceinline__ void ldsm4(u32 r[4], u32 a)
{
    asm volatile("ldmatrix.sync.aligned.m8n8.x4.shared.b16 {%0,%1,%2,%3}, [%4];"
        : "=r"(r[0]), "=r"(r[1]), "=r"(r[2]), "=r"(r[3]) : "r"(a));
}
__device__ __forceinline__ void ldsm4t(u32 r[4], u32 a)
{
    asm volatile("ldmatrix.sync.aligned.m8n8.x4.trans.shared.b16 {%0,%1,%2,%3}, [%4];"
        : "=r"(r[0]), "=r"(r[1]), "=r"(r[2]), "=r"(r[3]) : "r"(a));
}
__device__ __forceinline__ void cpa16(u32 s, const void* g)
{
    asm volatile("cp.async.ca.shared.global [%0], [%1], 16;" :: "r"(s), "l"(g));
}
#define CP_COMMIT() asm volatile("cp.async.commit_group;" ::: "memory")
#define CP_WAIT1()  asm volatile("cp.async.wait_group 1;" ::: "memory")
#define CP_WAIT0()  asm volatile("cp.async.wait_group 0;" ::: "memory")

// ---------------- split pre-pass -------------------------------------------
__global__ void split_kernel(const float4* __restrict__ src,
                             uint2* __restrict__ hi, uint2* __restrict__ lo, int n4)
{
    int i = blockIdx.x * blockDim.x + threadIdx.x;
    const int stride = gridDim.x * blockDim.x;
    for (; i < n4; i += stride) {
        float4 v = src[i];
        HL a = split2f(v.x, v.y), b = split2f(v.z, v.w);
        hi[i] = make_uint2(a.h, b.h);
        lo[i] = make_uint2(a.l, b.l);
    }
}

// ---------------- GEMM: C[8192,1024] = A @ W + bias ------------------------
// 128x128 tile, BK=32, 8 warps (2m x 4n). A [m][k] pitch 40; W [k][n] pitch 136.
#define BKP 40
#define NPW 136
#define ASZ (128 * BKP)               // 5120
#define WSZ (32 * NPW)                // 4352
#define GBUF (2 * ASZ + 2 * WSZ)      // 18944 elems per buffer

__device__ __forceinline__ void gemm_stage(
    u32 sbase, int buf,
    const u16* __restrict__ Ah_g, const u16* __restrict__ Al_g,
    const u16* __restrict__ Wh_g, const u16* __restrict__ Wl_g,
    int m0, int n0, int kt, int tid)
{
    const u32 db = sbase + buf * (GBUF * 2);
    const int a_row = tid >> 2, a_off = tid & 3;
    const int w_row = tid >> 4, w_off = tid & 15;
#pragma unroll
    for (int i = 0; i < 4; i++) {
        const u16* src = (i < 2) ? Ah_g : Al_g;
        const int row = a_row + 64 * (i & 1);
        cpa16(db + 2 * ((i >> 1) * ASZ + row * BKP + a_off * 8),
              src + (size_t)(m0 + row) * D_MODEL + kt * 32 + a_off * 8);
    }
#pragma unroll
    for (int i = 0; i < 4; i++) {
        const u16* src = (i < 2) ? Wh_g : Wl_g;
        const int row = w_row + 16 * (i & 1);
        cpa16(db + 2 * (2 * ASZ + (i >> 1) * WSZ + row * NPW + w_off * 8),
              src + (size_t)(kt * 32 + row) * D_MODEL + n0 + w_off * 8);
    }
    CP_COMMIT();
}

// MODE 0: fp32 output [M][1024]; MODE 1: headsplit bf16 hi/lo planes [bh][s][64]
template <int MODE>
__global__ void __launch_bounds__(256) gemm_tc(
    const u16* __restrict__ Ah_g, const u16* __restrict__ Al_g,
    const u16* __restrict__ Wh_g, const u16* __restrict__ Wl_g,
    const float* __restrict__ bias, float scale,
    float* __restrict__ Cf, u16* __restrict__ Ch, u16* __restrict__ Cl)
{
    extern __shared__ u16 smw[];
    const u32 sbase = (u32)__cvta_generic_to_shared(smw);

    const int m0 = blockIdx.y * 128, n0 = blockIdx.x * 128;
    const int tid = threadIdx.x, lane = tid & 31, warp = tid >> 5;
    const int g = lane >> 2, tig = lane & 3;
    const int wm = warp >> 2, wn = warp & 3;

    // fragment address bases
    const int rA = wm * 64 + (lane & 7) + ((lane >> 3) & 1) * 8;
    const int cA = (lane >> 4) * 8;
    const int rW = ((lane >> 3) & 1) * 8 + (lane & 7);
    const int cW = wn * 32 + (lane >> 4) * 8;

    float acc[4][4][4];
#pragma unroll
    for (int i = 0; i < 4; i++)
#pragma unroll
        for (int j = 0; j < 4; j++)
#pragma unroll
            for (int c = 0; c < 4; c++) acc[i][j][c] = 0.f;

    gemm_stage(sbase, 0, Ah_g, Al_g, Wh_g, Wl_g, m0, n0, 0, tid);

    for (int kt = 0; kt < 32; kt++) {
        const int buf = kt & 1;
        if (kt < 31) {
            gemm_stage(sbase, buf ^ 1, Ah_g, Al_g, Wh_g, Wl_g, m0, n0, kt + 1, tid);
            CP_WAIT1();
        } else {
            CP_WAIT0();
        }
        __syncthreads();

        const u32 db = sbase + buf * (GBUF * 2);
#pragma unroll
        for (int kk = 0; kk < 2; kk++) {
            u32 ah[4][4], al_[4][4];
#pragma unroll
            for (int ma = 0; ma < 4; ma++) {
                const u32 a = db + 2 * ((rA + ma * 16) * BKP + kk * 16 + cA);
                ldsm4(ah[ma], a);
                ldsm4(al_[ma], a + 2 * ASZ);
            }
            u32 bh[4][2], bl[4][2];
#pragma unroll
            for (int np = 0; np < 2; np++) {
                const u32 a = db + 2 * (2 * ASZ + (kk * 16 + rW) * NPW + cW + np * 16);
                u32 r[4];
                ldsm4t(r, a);
                bh[2*np][0] = r[0]; bh[2*np][1] = r[1];
                bh[2*np+1][0] = r[2]; bh[2*np+1][1] = r[3];
                ldsm4t(r, a + 2 * WSZ);
                bl[2*np][0] = r[0]; bl[2*np][1] = r[1];
                bl[2*np+1][0] = r[2]; bl[2*np+1][1] = r[3];
            }
#pragma unroll
            for (int ma = 0; ma < 4; ma++)
#pragma unroll
                for (int na = 0; na < 4; na++) {
                    mma_bf16(acc[ma][na], ah[ma], bh[na]);
                    mma_bf16(acc[ma][na], ah[ma], bl[na]);
                    mma_bf16(acc[ma][na], al_[ma], bh[na]);
                }
        }
        __syncthreads();
    }

    // epilogue
#pragma unroll
    for (int ma = 0; ma < 4; ma++) {
        const int m_r = m0 + wm * 64 + ma * 16 + g;
#pragma unroll
        for (int na = 0; na < 4; na++) {
            const int n = n0 + wn * 32 + na * 8 + 2 * tig;
            const float2 bv = *(const float2*)&bias[n];
            const float o0 = (acc[ma][na][0] + bv.x) * scale;
            const float o1 = (acc[ma][na][1] + bv.y) * scale;
            const float o2 = (acc[ma][na][2] + bv.x) * scale;
            const float o3 = (acc[ma][na][3] + bv.y) * scale;
            if (MODE == 0) {
                *(float2*)&Cf[(size_t)m_r * D_MODEL + n] = make_float2(o0, o1);
                *(float2*)&Cf[(size_t)(m_r + 8) * D_MODEL + n] = make_float2(o2, o3);
            } else {
                const int h = n >> 6, d = n & 63;
                const int b = m_r >> 11, s = m_r & 2047;
                const size_t i0 = (((size_t)(b * NHEAD + h)) * SEQ + s) * DEPTH + d;
                const size_t i1 = i0 + 8 * DEPTH;
                HL r0 = split2f(o0, o1), r1 = split2f(o2, o3);
                *(u32*)&Ch[i0] = r0.h; *(u32*)&Cl[i0] = r0.l;
                *(u32*)&Ch[i1] = r1.h; *(u32*)&Cl[i1] = r1.l;
            }
        }
    }
}

// ---------------- flash attention ------------------------------------------
// Block = (bh, 128-q tile). 8 warps x 16 q rows. 64-key chunks.
// K,V staged NATURAL ([s][d], [j][d]) as bf16 hi/lo planes, pitch 72.
// P stays in registers (C-fragment == A-fragment layout).
#define KP  72
#define PS  (64 * KP)       // 4608
#define ABUFE (4 * PS)      // 18432 elems per buffer

__device__ __forceinline__ void attn_stage(
    u32 sbase, int buf,
    const u16* __restrict__ Kh_g, const u16* __restrict__ Kl_g,
    const u16* __restrict__ Vh_g, const u16* __restrict__ Vl_g,
    int bh, int kc, int tid)
{
    const u32 db = sbase + buf * (ABUFE * 2);
#pragma unroll
    for (int i = 0; i < 8; i++) {
        const int plane = i >> 1;
        const u16* src = (plane == 0) ? Kh_g : (plane == 1) ? Kl_g
                       : (plane == 2) ? Vh_g : Vl_g;
        const int row = (tid >> 3) + 32 * (i & 1);
        cpa16(db + 2 * (plane * PS + row * KP + (tid & 7) * 8),
              src + ((size_t)bh * SEQ + kc + row) * DEPTH + (tid & 7) * 8);
    }
    CP_COMMIT();
}

__global__ void __launch_bounds__(256) attn_tc(
    const u16* __restrict__ Qh_g, const u16* __restrict__ Ql_g,
    const u16* __restrict__ Kh_g, const u16* __restrict__ Kl_g,
    const u16* __restrict__ Vh_g, const u16* __restrict__ Vl_g,
    u16* __restrict__ Oh, u16* __restrict__ Ol)
{
    extern __shared__ u16 sma[];
    const u32 sbase = (u32)__cvta_generic_to_shared(sma);

    const int bh = blockIdx.y, q0 = blockIdx.x * 128;
    const int tid = threadIdx.x, lane = tid & 31, warp = tid >> 5;
    const int g = lane >> 2, tig = lane & 3;
    const int w16 = warp * 16;

    // Q fragments from gmem planes (scale already folded at projection)
    u32 qfh[4][4], qfl[4][4];
    {
        const u16* Qbh = Qh_g + ((size_t)bh * SEQ + q0) * DEPTH;
        const u16* Qbl = Ql_g + ((size_t)bh * SEQ + q0) * DEPTH;
#pragma unroll
        for (int ks = 0; ks < 4; ks++) {
            const int c = ks * 16 + 2 * tig;
            qfh[ks][0] = *(const u32*)&Qbh[(w16 + g) * DEPTH + c];
            qfh[ks][1] = *(const u32*)&Qbh[(w16 + g + 8) * DEPTH + c];
            qfh[ks][2] = *(const u32*)&Qbh[(w16 + g) * DEPTH + c + 8];
            qfh[ks][3] = *(const u32*)&Qbh[(w16 + g + 8) * DEPTH + c + 8];
            qfl[ks][0] = *(const u32*)&Qbl[(w16 + g) * DEPTH + c];
            qfl[ks][1] = *(const u32*)&Qbl[(w16 + g + 8) * DEPTH + c];
            qfl[ks][2] = *(const u32*)&Qbl[(w16 + g) * DEPTH + c + 8];
            qfl[ks][3] = *(const u32*)&Qbl[(w16 + g + 8) * DEPTH + c + 8];
        }
    }

    float o[8][4];
#pragma unroll
    for (int na = 0; na < 8; na++)
#pragma unroll
        for (int c = 0; c < 4; c++) o[na][c] = 0.f;
    float m0r = -INFINITY, m1r = -INFINITY, l0 = 0.f, l1 = 0.f;

    // fragment address bases
    const int rK = (lane >> 4) * 8 + (lane & 7);   // n-row within np block (K)
    const int cK = ((lane >> 3) & 1) * 8;          // k-half (K)
    const int rV = ((lane >> 3) & 1) * 8 + (lane & 7); // j-row within ks block (V)
    const int cV = (lane >> 4) * 8;                // n-offset within np block (V)

    attn_stage(sbase, 0, Kh_g, Kl_g, Vh_g, Vl_g, bh, 0, tid);

    for (int kc = 0; kc < SEQ; kc += 64) {
        const int buf = (kc >> 6) & 1;
        if (kc + 64 < SEQ) {
            attn_stage(sbase, buf ^ 1, Kh_g, Kl_g, Vh_g, Vl_g, bh, kc + 64, tid);
            CP_WAIT1();
        } else {
            CP_WAIT0();
        }
        __syncthreads();
        const u32 db = sbase + buf * (ABUFE * 2);

        // ---- S = Q K^T ----
        float s[8][4];
#pragma unroll
        for (int na = 0; na < 8; na++)
#pragma unroll
            for (int c = 0; c < 4; c++) s[na][c] = 0.f;

#pragma unroll
        for (int ks = 0; ks < 4; ks++) {
#pragma unroll
            for (int np = 0; np < 4; np++) {
                const u32 a = db + 2 * ((np * 16 + rK) * KP + ks * 16 + cK);
                u32 rh[4], rl[4];
                ldsm4(rh, a);
                ldsm4(rl, a + 2 * PS);
                u32 b0h[2] = {rh[0], rh[1]}, b1h[2] = {rh[2], rh[3]};
                u32 b0l[2] = {rl[0], rl[1]}, b1l[2] = {rl[2], rl[3]};
                mma_bf16(s[2*np],   qfh[ks], b0h);
                mma_bf16(s[2*np],   qfh[ks], b0l);
                mma_bf16(s[2*np],   qfl[ks], b0h);
                mma_bf16(s[2*np+1], qfh[ks], b1h);
                mma_bf16(s[2*np+1], qfh[ks], b1l);
                mma_bf16(s[2*np+1], qfl[ks], b1h);
            }
        }

        // ---- online softmax (rows g, g+8; quad reduction) ----
        float mx0 = -INFINITY, mx1 = -INFINITY;
#pragma unroll
        for (int na = 0; na < 8; na++) {
            mx0 = fmaxf(mx0, fmaxf(s[na][0], s[na][1]));
            mx1 = fmaxf(mx1, fmaxf(s[na][2], s[na][3]));
        }
        mx0 = fmaxf(mx0, __shfl_xor_sync(0xffffffffu, mx0, 1));
        mx0 = fmaxf(mx0, __shfl_xor_sync(0xffffffffu, mx0, 2));
        mx1 = fmaxf(mx1, __shfl_xor_sync(0xffffffffu, mx1, 1));
        mx1 = fmaxf(mx1, __shfl_xor_sync(0xffffffffu, mx1, 2));

        const float mn0 = fmaxf(m0r, mx0), mn1 = fmaxf(m1r, mx1);
        const float a0 = __expf(m0r - mn0), a1 = __expf(m1r - mn1);
        m0r = mn0; m1r = mn1;

        float r0 = 0.f, r1 = 0.f;
#pragma unroll
        for (int na = 0; na < 8; na++) {
            s[na][0] = __expf(s[na][0] - mn0);
            s[na][1] = __expf(s[na][1] - mn0);
            s[na][2] = __expf(s[na][2] - mn1);
            s[na][3] = __expf(s[na][3] - mn1);
            r0 += s[na][0] + s[na][1];
            r1 += s[na][2] + s[na][3];
        }
        r0 += __shfl_xor_sync(0xffffffffu, r0, 1);
        r0 += __shfl_xor_sync(0xffffffffu, r0, 2);
        r1 += __shfl_xor_sync(0xffffffffu, r1, 1);
        r1 += __shfl_xor_sync(0xffffffffu, r1, 2);
        l0 = l0 * a0 + r0;
        l1 = l1 * a1 + r1;
#pragma unroll
        for (int na = 0; na < 8; na++) {
            o[na][0] *= a0; o[na][1] *= a0;
            o[na][2] *= a1; o[na][3] *= a1;
        }

        // ---- O += P V (P packed in registers from S fragments) ----
#pragma unroll
        for (int ks = 0; ks < 4; ks++) {
            HL p0 = split2f(s[2*ks][0],   s[2*ks][1]);
            HL p1 = split2f(s[2*ks][2],   s[2*ks][3]);
            HL p2 = split2f(s[2*ks+1][0], s[2*ks+1][1]);
            HL p3 = split2f(s[2*ks+1][2], s[2*ks+1][3]);
            u32 aph[4] = {p0.h, p1.h, p2.h, p3.h};
            u32 apl[4] = {p0.l, p1.l, p2.l, p3.l};
#pragma unroll
            for (int np = 0; np < 4; np++) {
                const u32 a = db + 2 * (2 * PS + (ks * 16 + rV) * KP + np * 16 + cV);
                u32 rh[4], rl[4];
                ldsm4t(rh, a);
                ldsm4t(rl, a + 2 * PS);
                u32 b0h[2] = {rh[0], rh[1]}, b1h[2] = {rh[2], rh[3]};
                u32 b0l[2] = {rl[0], rl[1]}, b1l[2] = {rl[2], rl[3]};
                mma_bf16(o[2*np],   aph, b0h);
                mma_bf16(o[2*np],   aph, b0l);
                mma_bf16(o[2*np],   apl, b0h);
                mma_bf16(o[2*np+1], aph, b1h);
                mma_bf16(o[2*np+1], aph, b1l);
                mma_bf16(o[2*np+1], apl, b1h);
            }
        }
        __syncthreads();
    }

    // ---- epilogue: normalize, split, write merged-layout bf16 planes ----
    const int b = bh >> 4, h = bh & 15;
    const float i0 = 1.f / l0, i1 = 1.f / l1;
    const int row0 = q0 + w16 + g;
    const size_t base0 = ((size_t)(b * SEQ + row0)) * D_MODEL + h * 64 + 2 * tig;
    const size_t base1 = base0 + (size_t)8 * D_MODEL;
#pragma unroll
    for (int na = 0; na < 8; na++) {
        HL r0 = split2f(o[na][0] * i0, o[na][1] * i0);
        HL r1 = split2f(o[na][2] * i1, o[na][3] * i1);
        *(u32*)&Oh[base0 + na * 8] = r0.h;
        *(u32*)&Ol[base0 + na * 8] = r0.l;
        *(u32*)&Oh[base1 + na * 8] = r1.h;
        *(u32*)&Ol[base1 + na * 8] = r1.l;
    }
}

// ---------------------------------------------------------------------------
extern "C" void kernel_launch(void* const* d_in, const int* in_sizes, int n_in,
                              void* d_out, int out_size)
{
    const float* v  = (const float*)d_in[0];
    const float* k  = (const float*)d_in[1];
    const float* q  = (const float*)d_in[2];
    const float* wq = (const float*)d_in[3];
    const float* bq = (const float*)d_in[4];
    const float* wk = (const float*)d_in[5];
    const float* bk = (const float*)d_in[6];
    const float* wv = (const float*)d_in[7];
    const float* bv = (const float*)d_in[8];
    const float* wo = (const float*)d_in[9];
    const float* bo = (const float*)d_in[10];
    float* out = (float*)d_out;

    u16 *xh, *xl, *wh, *wl, *ph, *pl, *oh, *ol;
    cudaGetSymbolAddress((void**)&xh, g_xh);
    cudaGetSymbolAddress((void**)&xl, g_xl);
    cudaGetSymbolAddress((void**)&wh, g_wh);
    cudaGetSymbolAddress((void**)&wl, g_wl);
    cudaGetSymbolAddress((void**)&ph, g_ph);
    cudaGetSymbolAddress((void**)&pl, g_pl);
    cudaGetSymbolAddress((void**)&oh, g_oh);
    cudaGetSymbolAddress((void**)&ol, g_ol);

    const int gemm_smem = 2 * GBUF * 2;    // 75776 B
    const int attn_smem = 2 * ABUFE * 2;   // 73728 B
    cudaFuncSetAttribute(gemm_tc<0>, cudaFuncAttributeMaxDynamicSharedMemorySize, gemm_smem);
    cudaFuncSetAttribute(gemm_tc<1>, cudaFuncAttributeMaxDynamicSharedMemorySize, gemm_smem);
    cudaFuncSetAttribute(attn_tc,    cudaFuncAttributeMaxDynamicSharedMemorySize, attn_smem);

    // 1) split inputs + weights into bf16 hi/lo planes
    split_kernel<<<2048, 256>>>((const float4*)q, (uint2*)(xh),           (uint2*)(xl),           INN / 4);
    split_kernel<<<2048, 256>>>((const float4*)k, (uint2*)(xh + (size_t)INN),   (uint2*)(xl + (size_t)INN),   INN / 4);
    split_kernel<<<2048, 256>>>((const float4*)v, (uint2*)(xh + (size_t)2*INN), (uint2*)(xl + (size_t)2*INN), INN / 4);
    split_kernel<<<1024, 256>>>((const float4*)wq, (uint2*)(wh),                (uint2*)(wl),                WN / 4);
    split_kernel<<<1024, 256>>>((const float4*)wk, (uint2*)(wh + (size_t)WN),   (uint2*)(wl + (size_t)WN),   WN / 4);
    split_kernel<<<1024, 256>>>((const float4*)wv, (uint2*)(wh + (size_t)2*WN), (uint2*)(wl + (size_t)2*WN), WN / 4);
    split_kernel<<<1024, 256>>>((const float4*)wo, (uint2*)(wh + (size_t)3*WN), (uint2*)(wl + (size_t)3*WN), WN / 4);

    const dim3 gg(D_MODEL / 128, MROWS / 128);   // (8, 64)

    // 2) projections (headsplit bf16 planes; Q gets 1/sqrt(depth) folded in)
    gemm_tc<1><<<gg, 256, gemm_smem>>>(xh, xl, wh, wl, bq, 0.125f,
                                       nullptr, ph, pl);
    gemm_tc<1><<<gg, 256, gemm_smem>>>(xh + (size_t)INN, xl + (size_t)INN,
                                       wh + (size_t)WN, wl + (size_t)WN, bk, 1.f,
                                       nullptr, ph + (size_t)PROJN, pl + (size_t)PROJN);
    gemm_tc<1><<<gg, 256, gemm_smem>>>(xh + (size_t)2*INN, xl + (size_t)2*INN,
                                       wh + (size_t)2*WN, wl + (size_t)2*WN, bv, 1.f,
                                       nullptr, ph + (size_t)2*PROJN, pl + (size_t)2*PROJN);

    // 3) attention
    attn_tc<<<dim3(SEQ / 128, NBH), 256, attn_smem>>>(
        ph, pl,
        ph + (size_t)PROJN, pl + (size_t)PROJN,
        ph + (size_t)2*PROJN, pl + (size_t)2*PROJN,
        oh, ol);

    // 4) output projection -> fp32 d_out
    gemm_tc<0><<<gg, 256, gemm_smem>>>(oh, ol, wh + (size_t)3*WN, wl + (size_t)3*WN,
                                       bo, 1.f, out, nullptr, nullptr);
}

// round 7
// speedup vs baseline: 3.6386x; 1.0777x over previous
#include <cuda_runtime.h>
#include <cuda_bf16.h>
#include <math.h>

typedef unsigned int u32;
typedef unsigned short u16;

#define D_MODEL 1024
#define NHEAD   16
#define DEPTH   64
#define BATCH   4
#define SEQ     2048
#define MROWS   (BATCH * SEQ)       // 8192
#define NBH     (BATCH * NHEAD)     // 64
#define INN     (MROWS * D_MODEL)   // 8388608
#define WN      (D_MODEL * D_MODEL)
#define PROJN   (NBH * SEQ * DEPTH) // 8388608

// ---------------- global scratch (alloc-free rule) -------------------------
__device__ u16 g_xh[3][INN],  g_xl[3][INN];    // split q/k/v inputs
__device__ u16 g_wh[4][WN],   g_wl[4][WN];     // split wq/wk/wv/wo [k][n]
__device__ u16 g_ph[3][PROJN], g_pl[3][PROJN]; // projected qh/kh/vh planes
__device__ u16 g_oh[INN],     g_ol[INN];       // attention output planes

// ---------------- primitives ----------------------------------------------
__device__ __forceinline__ void mma_bf16(float c[4], const u32 a[4], const u32 b[2])
{
    asm("mma.sync.aligned.m16n8k16.row.col.f32.bf16.bf16.f32 "
        "{%0,%1,%2,%3}, {%4,%5,%6,%7}, {%8,%9}, {%0,%1,%2,%3};"
        : "+f"(c[0]), "+f"(c[1]), "+f"(c[2]), "+f"(c[3])
        : "r"(a[0]), "r"(a[1]), "r"(a[2]), "r"(a[3]), "r"(b[0]), "r"(b[1]));
}

struct HL { u32 h, l; };
__device__ __forceinline__ HL split2f(float x, float y)
{
    HL r;
    asm("cvt.rn.bf16x2.f32 %0, %1, %2;" : "=r"(r.h) : "f"(y), "f"(x));
    float xh = __uint_as_float(r.h << 16);
    float yh = __uint_as_float(r.h & 0xffff0000u);
    asm("cvt.rn.bf16x2.f32 %0, %1, %2;" : "=r"(r.l) : "f"(y - yh), "f"(x - xh));
    return r;
}

__device__ __forceinline__ void ldsm4(u32 r[4], u32 a)
{
    asm volatile("ldmatrix.sync.aligned.m8n8.x4.shared.b16 {%0,%1,%2,%3}, [%4];"
        : "=r"(r[0]), "=r"(r[1]), "=r"(r[2]), "=r"(r[3]) : "r"(a));
}
__device__ __forceinline__ void ldsm4t(u32 r[4], u32 a)
{
    asm volatile("ldmatrix.sync.aligned.m8n8.x4.trans.shared.b16 {%0,%1,%2,%3}, [%4];"
        : "=r"(r[0]), "=r"(r[1]), "=r"(r[2]), "=r"(r[3]) : "r"(a));
}
__device__ __forceinline__ void cpa16(u32 s, const void* g)
{
    asm volatile("cp.async.ca.shared.global [%0], [%1], 16;" :: "r"(s), "l"(g));
}
#define CP_COMMIT() asm volatile("cp.async.commit_group;" ::: "memory")
#define CP_WAIT1()  asm volatile("cp.async.wait_group 1;" ::: "memory")
#define CP_WAIT0()  asm volatile("cp.async.wait_group 0;" ::: "memory")

// ---------------- split pre-passes (fused across tensors) ------------------
__global__ void split3_kernel(const float4* __restrict__ s0,
                              const float4* __restrict__ s1,
                              const float4* __restrict__ s2,
                              uint2* __restrict__ hi, uint2* __restrict__ lo, int n4)
{
    const int z = blockIdx.z;
    const float4* src = (z == 0) ? s0 : (z == 1) ? s1 : s2;
    uint2* h = hi + (size_t)z * n4;
    uint2* l = lo + (size_t)z * n4;
    int i = blockIdx.x * blockDim.x + threadIdx.x;
    const int stride = gridDim.x * blockDim.x;
    for (; i < n4; i += stride) {
        float4 v = src[i];
        HL a = split2f(v.x, v.y), b = split2f(v.z, v.w);
        h[i] = make_uint2(a.h, b.h);
        l[i] = make_uint2(a.l, b.l);
    }
}

__global__ void split4_kernel(const float4* __restrict__ s0,
                              const float4* __restrict__ s1,
                              const float4* __restrict__ s2,
                              const float4* __restrict__ s3,
                              uint2* __restrict__ hi, uint2* __restrict__ lo, int n4)
{
    const int z = blockIdx.z;
    const float4* src = (z == 0) ? s0 : (z == 1) ? s1 : (z == 2) ? s2 : s3;
    uint2* h = hi + (size_t)z * n4;
    uint2* l = lo + (size_t)z * n4;
    int i = blockIdx.x * blockDim.x + threadIdx.x;
    const int stride = gridDim.x * blockDim.x;
    for (; i < n4; i += stride) {
        float4 v = src[i];
        HL a = split2f(v.x, v.y), b = split2f(v.z, v.w);
        h[i] = make_uint2(a.h, b.h);
        l[i] = make_uint2(a.l, b.l);
    }
}

// ---------------- GEMM core (HMMA, R4-proven) ------------------------------
// 128x128 tile, BK=32, 8 warps (2m x 4n). A [m][k] pitch 40; W [k][n] pitch 136.
#define BKP 40
#define NPW 136
#define ASZ (128 * BKP)               // 5120
#define WSZ (32 * NPW)                // 4352
#define GBUF (2 * ASZ + 2 * WSZ)      // 18944 elems per buffer

__device__ __forceinline__ void gemm_stage(
    u32 sbase, int buf,
    const u16* __restrict__ Ah_g, const u16* __restrict__ Al_g,
    const u16* __restrict__ Wh_g, const u16* __restrict__ Wl_g,
    int m0, int n0, int kt, int tid)
{
    const u32 db = sbase + buf * (GBUF * 2);
    const int a_row = tid >> 2, a_off = tid & 3;
    const int w_row = tid >> 4, w_off = tid & 15;
#pragma unroll
    for (int i = 0; i < 4; i++) {
        const u16* src = (i < 2) ? Ah_g : Al_g;
        const int row = a_row + 64 * (i & 1);
        cpa16(db + 2 * ((i >> 1) * ASZ + row * BKP + a_off * 8),
              src + (size_t)(m0 + row) * D_MODEL + kt * 32 + a_off * 8);
    }
#pragma unroll
    for (int i = 0; i < 4; i++) {
        const u16* src = (i < 2) ? Wh_g : Wl_g;
        const int row = w_row + 16 * (i & 1);
        cpa16(db + 2 * (2 * ASZ + (i >> 1) * WSZ + row * NPW + w_off * 8),
              src + (size_t)(kt * 32 + row) * D_MODEL + n0 + w_off * 8);
    }
    CP_COMMIT();
}

// body shared by both GEMM kernels; MODE 0: fp32 out, MODE 1: headsplit planes
template <int MODE>
__device__ __forceinline__ void gemm_body(
    const u16* __restrict__ Ah_g, const u16* __restrict__ Al_g,
    const u16* __restrict__ Wh_g, const u16* __restrict__ Wl_g,
    const float* __restrict__ bias, float scale,
    float* __restrict__ Cf, u16* __restrict__ Ch, u16* __restrict__ Cl)
{
    extern __shared__ u16 smw[];
    const u32 sbase = (u32)__cvta_generic_to_shared(smw);

    const int m0 = blockIdx.y * 128, n0 = blockIdx.x * 128;
    const int tid = threadIdx.x, lane = tid & 31, warp = tid >> 5;
    const int g = lane >> 2, tig = lane & 3;
    const int wm = warp >> 2, wn = warp & 3;

    const int rA = wm * 64 + (lane & 7) + ((lane >> 3) & 1) * 8;
    const int cA = (lane >> 4) * 8;
    const int rW = ((lane >> 3) & 1) * 8 + (lane & 7);
    const int cW = wn * 32 + (lane >> 4) * 8;

    float acc[4][4][4];
#pragma unroll
    for (int i = 0; i < 4; i++)
#pragma unroll
        for (int j = 0; j < 4; j++)
#pragma unroll
            for (int c = 0; c < 4; c++) acc[i][j][c] = 0.f;

    gemm_stage(sbase, 0, Ah_g, Al_g, Wh_g, Wl_g, m0, n0, 0, tid);

    for (int kt = 0; kt < 32; kt++) {
        const int buf = kt & 1;
        if (kt < 31) {
            gemm_stage(sbase, buf ^ 1, Ah_g, Al_g, Wh_g, Wl_g, m0, n0, kt + 1, tid);
            CP_WAIT1();
        } else {
            CP_WAIT0();
        }
        __syncthreads();

        const u32 db = sbase + buf * (GBUF * 2);
#pragma unroll
        for (int kk = 0; kk < 2; kk++) {
            u32 ah[4][4], al_[4][4];
#pragma unroll
            for (int ma = 0; ma < 4; ma++) {
                const u32 a = db + 2 * ((rA + ma * 16) * BKP + kk * 16 + cA);
                ldsm4(ah[ma], a);
                ldsm4(al_[ma], a + 2 * ASZ);
            }
            u32 bh[4][2], bl[4][2];
#pragma unroll
            for (int np = 0; np < 2; np++) {
                const u32 a = db + 2 * (2 * ASZ + (kk * 16 + rW) * NPW + cW + np * 16);
                u32 r[4];
                ldsm4t(r, a);
                bh[2*np][0] = r[0]; bh[2*np][1] = r[1];
                bh[2*np+1][0] = r[2]; bh[2*np+1][1] = r[3];
                ldsm4t(r, a + 2 * WSZ);
                bl[2*np][0] = r[0]; bl[2*np][1] = r[1];
                bl[2*np+1][0] = r[2]; bl[2*np+1][1] = r[3];
            }
#pragma unroll
            for (int ma = 0; ma < 4; ma++)
#pragma unroll
                for (int na = 0; na < 4; na++) {
                    mma_bf16(acc[ma][na], ah[ma], bh[na]);
                    mma_bf16(acc[ma][na], ah[ma], bl[na]);
                    mma_bf16(acc[ma][na], al_[ma], bh[na]);
                }
        }
        __syncthreads();
    }

#pragma unroll
    for (int ma = 0; ma < 4; ma++) {
        const int m_r = m0 + wm * 64 + ma * 16 + g;
#pragma unroll
        for (int na = 0; na < 4; na++) {
            const int n = n0 + wn * 32 + na * 8 + 2 * tig;
            const float2 bv = *(const float2*)&bias[n];
            const float o0 = (acc[ma][na][0] + bv.x) * scale;
            const float o1 = (acc[ma][na][1] + bv.y) * scale;
            const float o2 = (acc[ma][na][2] + bv.x) * scale;
            const float o3 = (acc[ma][na][3] + bv.y) * scale;
            if (MODE == 0) {
                *(float2*)&Cf[(size_t)m_r * D_MODEL + n] = make_float2(o0, o1);
                *(float2*)&Cf[(size_t)(m_r + 8) * D_MODEL + n] = make_float2(o2, o3);
            } else {
                const int h = n >> 6, d = n & 63;
                const int b = m_r >> 11, s = m_r & 2047;
                const size_t i0 = (((size_t)(b * NHEAD + h)) * SEQ + s) * DEPTH + d;
                const size_t i1 = i0 + 8 * DEPTH;
                HL r0 = split2f(o0, o1), r1 = split2f(o2, o3);
                *(u32*)&Ch[i0] = r0.h; *(u32*)&Cl[i0] = r0.l;
                *(u32*)&Ch[i1] = r1.h; *(u32*)&Cl[i1] = r1.l;
            }
        }
    }
}

// fused Q/K/V projections: blockIdx.z selects tensor; Q gets scale 0.125
__global__ void __launch_bounds__(256, 2) gemm_proj(
    const u16* __restrict__ xh, const u16* __restrict__ xl,
    const u16* __restrict__ wh, const u16* __restrict__ wl,
    const float* __restrict__ bq, const float* __restrict__ bk,
    const float* __restrict__ bv,
    u16* __restrict__ ph, u16* __restrict__ pl)
{
    const int z = blockIdx.z;
    const float* bias = (z == 0) ? bq : (z == 1) ? bk : bv;
    gemm_body<1>(xh + (size_t)z * INN, xl + (size_t)z * INN,
                 wh + (size_t)z * WN,  wl + (size_t)z * WN,
                 bias, (z == 0) ? 0.125f : 1.f,
                 nullptr, ph + (size_t)z * PROJN, pl + (size_t)z * PROJN);
}

__global__ void __launch_bounds__(256, 2) gemm_out(
    const u16* __restrict__ Ah, const u16* __restrict__ Al,
    const u16* __restrict__ Wh, const u16* __restrict__ Wl,
    const float* __restrict__ bias, float* __restrict__ Cf)
{
    gemm_body<0>(Ah, Al, Wh, Wl, bias, 1.f, Cf, nullptr, nullptr);
}

// ---------------- flash attention (HMMA, 2 CTAs/SM) ------------------------
#define KP  72
#define PS  (64 * KP)
#define ABUFE (4 * PS)

__device__ __forceinline__ void attn_stage(
    u32 sbase, int buf,
    const u16* __restrict__ Kh_g, const u16* __restrict__ Kl_g,
    const u16* __restrict__ Vh_g, const u16* __restrict__ Vl_g,
    int bh, int kc, int tid)
{
    const u32 db = sbase + buf * (ABUFE * 2);
#pragma unroll
    for (int i = 0; i < 8; i++) {
        const int plane = i >> 1;
        const u16* src = (plane == 0) ? Kh_g : (plane == 1) ? Kl_g
                       : (plane == 2) ? Vh_g : Vl_g;
        const int row = (tid >> 3) + 32 * (i & 1);
        cpa16(db + 2 * (plane * PS + row * KP + (tid & 7) * 8),
              src + ((size_t)bh * SEQ + kc + row) * DEPTH + (tid & 7) * 8);
    }
    CP_COMMIT();
}

__global__ void __launch_bounds__(256, 2) attn_tc(
    const u16* __restrict__ Qh_g, const u16* __restrict__ Ql_g,
    const u16* __restrict__ Kh_g, const u16* __restrict__ Kl_g,
    const u16* __restrict__ Vh_g, const u16* __restrict__ Vl_g,
    u16* __restrict__ Oh, u16* __restrict__ Ol)
{
    extern __shared__ u16 sma[];
    const u32 sbase = (u32)__cvta_generic_to_shared(sma);

    const int bh = blockIdx.y, q0 = blockIdx.x * 128;
    const int tid = threadIdx.x, lane = tid & 31, warp = tid >> 5;
    const int g = lane >> 2, tig = lane & 3;
    const int w16 = warp * 16;

    u32 qfh[4][4], qfl[4][4];
    {
        const u16* Qbh = Qh_g + ((size_t)bh * SEQ + q0) * DEPTH;
        const u16* Qbl = Ql_g + ((size_t)bh * SEQ + q0) * DEPTH;
#pragma unroll
        for (int ks = 0; ks < 4; ks++) {
            const int c = ks * 16 + 2 * tig;
            qfh[ks][0] = *(const u32*)&Qbh[(w16 + g) * DEPTH + c];
            qfh[ks][1] = *(const u32*)&Qbh[(w16 + g + 8) * DEPTH + c];
            qfh[ks][2] = *(const u32*)&Qbh[(w16 + g) * DEPTH + c + 8];
            qfh[ks][3] = *(const u32*)&Qbh[(w16 + g + 8) * DEPTH + c + 8];
            qfl[ks][0] = *(const u32*)&Qbl[(w16 + g) * DEPTH + c];
            qfl[ks][1] = *(const u32*)&Qbl[(w16 + g + 8) * DEPTH + c];
            qfl[ks][2] = *(const u32*)&Qbl[(w16 + g) * DEPTH + c + 8];
            qfl[ks][3] = *(const u32*)&Qbl[(w16 + g + 8) * DEPTH + c + 8];
        }
    }

    float o[8][4];
#pragma unroll
    for (int na = 0; na < 8; na++)
#pragma unroll
        for (int c = 0; c < 4; c++) o[na][c] = 0.f;
    float m0r = -INFINITY, m1r = -INFINITY, l0 = 0.f, l1 = 0.f;

    const int rK = (lane >> 4) * 8 + (lane & 7);
    const int cK = ((lane >> 3) & 1) * 8;
    const int rV = ((lane >> 3) & 1) * 8 + (lane & 7);
    const int cV = (lane >> 4) * 8;

    attn_stage(sbase, 0, Kh_g, Kl_g, Vh_g, Vl_g, bh, 0, tid);

    for (int kc = 0; kc < SEQ; kc += 64) {
        const int buf = (kc >> 6) & 1;
        if (kc + 64 < SEQ) {
            attn_stage(sbase, buf ^ 1, Kh_g, Kl_g, Vh_g, Vl_g, bh, kc + 64, tid);
            CP_WAIT1();
        } else {
            CP_WAIT0();
        }
        __syncthreads();
        const u32 db = sbase + buf * (ABUFE * 2);

        float s[8][4];
#pragma unroll
        for (int na = 0; na < 8; na++)
#pragma unroll
            for (int c = 0; c < 4; c++) s[na][c] = 0.f;

#pragma unroll
        for (int ks = 0; ks < 4; ks++) {
#pragma unroll
            for (int np = 0; np < 4; np++) {
                const u32 a = db + 2 * ((np * 16 + rK) * KP + ks * 16 + cK);
                u32 rh[4], rl[4];
                ldsm4(rh, a);
                ldsm4(rl, a + 2 * PS);
                u32 b0h[2] = {rh[0], rh[1]}, b1h[2] = {rh[2], rh[3]};
                u32 b0l[2] = {rl[0], rl[1]}, b1l[2] = {rl[2], rl[3]};
                mma_bf16(s[2*np],   qfh[ks], b0h);
                mma_bf16(s[2*np],   qfh[ks], b0l);
                mma_bf16(s[2*np],   qfl[ks], b0h);
                mma_bf16(s[2*np+1], qfh[ks], b1h);
                mma_bf16(s[2*np+1], qfh[ks], b1l);
                mma_bf16(s[2*np+1], qfl[ks], b1h);
            }
        }

        float mx0 = -INFINITY, mx1 = -INFINITY;
#pragma unroll
        for (int na = 0; na < 8; na++) {
            mx0 = fmaxf(mx0, fmaxf(s[na][0], s[na][1]));
            mx1 = fmaxf(mx1, fmaxf(s[na][2], s[na][3]));
        }
        mx0 = fmaxf(mx0, __shfl_xor_sync(0xffffffffu, mx0, 1));
        mx0 = fmaxf(mx0, __shfl_xor_sync(0xffffffffu, mx0, 2));
        mx1 = fmaxf(mx1, __shfl_xor_sync(0xffffffffu, mx1, 1));
        mx1 = fmaxf(mx1, __shfl_xor_sync(0xffffffffu, mx1, 2));

        const float mn0 = fmaxf(m0r, mx0), mn1 = fmaxf(m1r, mx1);
        const float a0 = __expf(m0r - mn0), a1 = __expf(m1r - mn1);
        m0r = mn0; m1r = mn1;

        float r0 = 0.f, r1 = 0.f;
#pragma unroll
        for (int na = 0; na < 8; na++) {
            s[na][0] = __expf(s[na][0] - mn0);
            s[na][1] = __expf(s[na][1] - mn0);
            s[na][2] = __expf(s[na][2] - mn1);
            s[na][3] = __expf(s[na][3] - mn1);
            r0 += s[na][0] + s[na][1];
            r1 += s[na][2] + s[na][3];
        }
        r0 += __shfl_xor_sync(0xffffffffu, r0, 1);
        r0 += __shfl_xor_sync(0xffffffffu, r0, 2);
        r1 += __shfl_xor_sync(0xffffffffu, r1, 1);
        r1 += __shfl_xor_sync(0xffffffffu, r1, 2);
        l0 = l0 * a0 + r0;
        l1 = l1 * a1 + r1;
#pragma unroll
        for (int na = 0; na < 8; na++) {
            o[na][0] *= a0; o[na][1] *= a0;
            o[na][2] *= a1; o[na][3] *= a1;
        }

#pragma unroll
        for (int ks = 0; ks < 4; ks++) {
            HL p0 = split2f(s[2*ks][0],   s[2*ks][1]);
            HL p1 = split2f(s[2*ks][2],   s[2*ks][3]);
            HL p2 = split2f(s[2*ks+1][0], s[2*ks+1][1]);
            HL p3 = split2f(s[2*ks+1][2], s[2*ks+1][3]);
            u32 aph[4] = {p0.h, p1.h, p2.h, p3.h};
            u32 apl[4] = {p0.l, p1.l, p2.l, p3.l};
#pragma unroll
            for (int np = 0; np < 4; np++) {
                const u32 a = db + 2 * (2 * PS + (ks * 16 + rV) * KP + np * 16 + cV);
                u32 rh[4], rl[4];
                ldsm4t(rh, a);
                ldsm4t(rl, a + 2 * PS);
                u32 b0h[2] = {rh[0], rh[1]}, b1h[2] = {rh[2], rh[3]};
                u32 b0l[2] = {rl[0], rl[1]}, b1l[2] = {rl[2], rl[3]};
                mma_bf16(o[2*np],   aph, b0h);
                mma_bf16(o[2*np],   aph, b0l);
                mma_bf16(o[2*np],   apl, b0h);
                mma_bf16(o[2*np+1], aph, b1h);
                mma_bf16(o[2*np+1], aph, b1l);
                mma_bf16(o[2*np+1], apl, b1h);
            }
        }
        __syncthreads();
    }

    const int b = bh >> 4, h = bh & 15;
    const float i0 = 1.f / l0, i1 = 1.f / l1;
    const int row0 = q0 + w16 + g;
    const size_t base0 = ((size_t)(b * SEQ + row0)) * D_MODEL + h * 64 + 2 * tig;
    const size_t base1 = base0 + (size_t)8 * D_MODEL;
#pragma unroll
    for (int na = 0; na < 8; na++) {
        HL r0 = split2f(o[na][0] * i0, o[na][1] * i0);
        HL r1 = split2f(o[na][2] * i1, o[na][3] * i1);
        *(u32*)&Oh[base0 + na * 8] = r0.h;
        *(u32*)&Ol[base0 + na * 8] = r0.l;
        *(u32*)&Oh[base1 + na * 8] = r1.h;
        *(u32*)&Ol[base1 + na * 8] = r1.l;
    }
}

// ---------------------------------------------------------------------------
extern "C" void kernel_launch(void* const* d_in, const int* in_sizes, int n_in,
                              void* d_out, int out_size)
{
    const float* v  = (const float*)d_in[0];
    const float* k  = (const float*)d_in[1];
    const float* q  = (const float*)d_in[2];
    const float* wq = (const float*)d_in[3];
    const float* bq = (const float*)d_in[4];
    const float* wk = (const float*)d_in[5];
    const float* bk = (const float*)d_in[6];
    const float* wv = (const float*)d_in[7];
    const float* bv = (const float*)d_in[8];
    const float* wo = (const float*)d_in[9];
    const float* bo = (const float*)d_in[10];
    float* out = (float*)d_out;

    u16 *xh, *xl, *wh, *wl, *ph, *pl, *oh, *ol;
    cudaGetSymbolAddress((void**)&xh, g_xh);
    cudaGetSymbolAddress((void**)&xl, g_xl);
    cudaGetSymbolAddress((void**)&wh, g_wh);
    cudaGetSymbolAddress((void**)&wl, g_wl);
    cudaGetSymbolAddress((void**)&ph, g_ph);
    cudaGetSymbolAddress((void**)&pl, g_pl);
    cudaGetSymbolAddress((void**)&oh, g_oh);
    cudaGetSymbolAddress((void**)&ol, g_ol);

    const int gemm_smem = 2 * GBUF * 2;    // 75776 B
    const int attn_smem = 2 * ABUFE * 2;   // 73728 B
    cudaFuncSetAttribute(gemm_proj, cudaFuncAttributeMaxDynamicSharedMemorySize, gemm_smem);
    cudaFuncSetAttribute(gemm_out,  cudaFuncAttributeMaxDynamicSharedMemorySize, gemm_smem);
    cudaFuncSetAttribute(attn_tc,   cudaFuncAttributeMaxDynamicSharedMemorySize, attn_smem);

    // 1) split inputs (grid.z selects q/k/v) and weights (grid.z selects wq..wo)
    split3_kernel<<<dim3(1024, 1, 3), 256>>>((const float4*)q, (const float4*)k,
                                             (const float4*)v,
                                             (uint2*)xh, (uint2*)xl, INN / 4);
    split4_kernel<<<dim3(512, 1, 4), 256>>>((const float4*)wq, (const float4*)wk,
                                            (const float4*)wv, (const float4*)wo,
                                            (uint2*)wh, (uint2*)wl, WN / 4);

    // 2) fused Q/K/V projections (one launch, grid.z = 3)
    gemm_proj<<<dim3(D_MODEL / 128, MROWS / 128, 3), 256, gemm_smem>>>(
        xh, xl, wh, wl, bq, bk, bv, ph, pl);

    // 3) attention
    attn_tc<<<dim3(SEQ / 128, NBH), 256, attn_smem>>>(
        ph, pl,
        ph + (size_t)PROJN, pl + (size_t)PROJN,
        ph + (size_t)2*PROJN, pl + (size_t)2*PROJN,
        oh, ol);

    // 4) output projection -> fp32 d_out
    gemm_out<<<dim3(D_MODEL / 128, MROWS / 128), 256, gemm_smem>>>(
        oh, ol, wh + (size_t)3*WN, wl + (size_t)3*WN, bo, out);
}